// round 6
// baseline (speedup 1.0000x reference)
#include <cuda_runtime.h>
#include <cstddef>

// Problem constants
//   x  : (16, 2048, 64, 64) f32
//   W1 : (16, 128, 2048)    f32
//   W2 : (16, 2048, 128)    f32
//   out: (16, 16, 2048) f32
#define B_ 16
#define C_ 2048
#define P_ 16
#define CR_ 128
#define NPATCH 32768
#define NT 512

// Scratch (__device__ globals: allocation-free rule)
__device__ float    g_yT[C_ * B_];               // [c][b] patch means
__device__ float    g_hp[4 * P_ * B_ * CR_];     // 4-slice split-K partial h
__device__ unsigned g_bar[4];                    // grid-barrier counters

// f32x2 packed helpers -------------------------------------------------------
__device__ __forceinline__ void fma2(unsigned long long& d,
                                     unsigned long long a,
                                     unsigned long long b) {
    asm("fma.rn.f32x2 %0, %1, %2, %0;" : "+l"(d) : "l"(a), "l"(b));
}
__device__ __forceinline__ void add2(unsigned long long& d, unsigned long long v) {
    asm("add.rn.f32x2 %0, %0, %1;" : "+l"(d) : "l"(v));
}
__device__ __forceinline__ unsigned long long dup2(float w) {
    unsigned long long r;
    asm("mov.b64 %0, {%1, %1};" : "=l"(r) : "f"(w));
    return r;
}
__device__ __forceinline__ float2 unpack2(unsigned long long v) {
    float lo, hi;
    asm("mov.b64 {%0, %1}, %2;" : "=f"(lo), "=f"(hi) : "l"(v));
    return make_float2(lo, hi);
}

// grid barrier (all nblk blocks co-resident by construction) -----------------
__device__ __forceinline__ void grid_barrier(int ph, int nblk) {
    __syncthreads();
    if (threadIdx.x == 0) {
        __threadfence();
        atomicAdd(&g_bar[ph], 1u);
        while (*(volatile unsigned*)&g_bar[ph] < (unsigned)nblk) {
            __nanosleep(20);
        }
    }
    __syncthreads();
    __threadfence();
}

__global__ void k_init() {
    if (threadIdx.x < 4) g_bar[threadIdx.x] = 0u;
}

// -----------------------------------------------------------------------------
// Shared memory (floats):
//   phase B: w1sh[32][1024] (128 KB) | ysh4[4][YS] float4 (65.7 KB)
//   phase C: w2sh[256][W2S] (135 KB) | hsh[2048] (8 KB)
#define YS  1026
#define W2S 132
#define SMEM_BYTES (32 * 1024 * 4 + 4 * YS * 16)    // 196736 B

__global__ void __launch_bounds__(NT, 1)
k_fused(const float* __restrict__ x, const float* __restrict__ W1,
        const float* __restrict__ W2, float* __restrict__ out, int nblk) {
    extern __shared__ float sm[];
    const int tid  = threadIdx.x;
    const int warp = tid >> 5;
    const int lane = tid & 31;
    const int bid  = blockIdx.x;

    // ===== W1 tile prefetch via cp.async (overlaps phase A) =================
    // tile: mtile = bid>>1 (32 rows), half = bid&1 (1024-c half). 128 tiles.
    if (bid < 128) {
        const int m0    = (bid >> 1) * 32;
        const int cbase = (bid & 1) * 1024;
#pragma unroll
        for (int k = 0; k < 16; ++k) {
            const int idx  = tid + k * NT;     // float4 index over 32x256
            const int row  = idx >> 8;
            const int quad = idx & 255;
            unsigned sa = (unsigned)__cvta_generic_to_shared(
                &sm[row * 1024 + quad * 4]);
            asm volatile("cp.async.cg.shared.global [%0], [%1], 16;"
                         :: "r"(sa),
                            "l"(W1 + (size_t)(m0 + row) * C_ + cbase + quad * 4));
        }
        asm volatile("cp.async.commit_group;");
    }

    // ===== Phase A: 16x16 patch means =======================================
    {
        const int gw   = bid * 16 + warp;        // global warp id
        const int step = nblk * 16 * 4;
        const int g    = lane >> 3;              // patch within warp
        const int sub  = lane & 7;
        for (int patch = gw * 4 + g; patch < NPATCH; patch += step) {
            const float* base = x + (size_t)patch * 4096 + 16 * 64 + 16;
            float s = 0.f;
#pragma unroll
            for (int t = 0; t < 8; ++t) {
                const int j = sub + t * 8;
                const float4 v = __ldcs(reinterpret_cast<const float4*>(
                    base + (j >> 2) * 64 + (j & 3) * 4));
                s += (v.x + v.y) + (v.z + v.w);
            }
            s += __shfl_xor_sync(0xffffffffu, s, 4);
            s += __shfl_xor_sync(0xffffffffu, s, 2);
            s += __shfl_xor_sync(0xffffffffu, s, 1);
            if (sub == 0) {
                const int b = patch >> 11;
                const int c = patch & 2047;
                g_yT[c * B_ + b] = s * (1.f / 256.f);
            }
        }
    }

    grid_barrier(0, nblk);

    // ===== Phase B: partial h, warp = (4 rows, 512-c quarter) ===============
    if (bid < 128) {
        float*  w1sh = sm;
        float4* ysh4 = reinterpret_cast<float4*>(sm + 32 * 1024);
        const int m0    = (bid >> 1) * 32;
        const int half  = bid & 1;
        const int cbase = half * 1024;
        const int rq    = warp >> 1;            // row-quad 0..7
        const int sub   = warp & 1;             // c-sub-half 0..1

        // stage y half: ysh4[bq][c'] <- yT[(cbase+c')*16 + 4bq .. +3]
#pragma unroll
        for (int k = 0; k < 8; ++k) {
            const int idx = tid + k * NT;
            const int c   = idx >> 2;
            const int bq  = idx & 3;
            ysh4[bq * YS + c] = *reinterpret_cast<const float4*>(
                &g_yT[(size_t)(cbase + c) * B_ + bq * 4]);
        }
        asm volatile("cp.async.wait_group 0;");
        __syncthreads();

        unsigned long long acc[4][4][2];
#pragma unroll
        for (int r = 0; r < 4; ++r)
#pragma unroll
            for (int bq = 0; bq < 4; ++bq) { acc[r][bq][0] = 0ull; acc[r][bq][1] = 0ull; }

#pragma unroll 4
        for (int q = 0; q < 16; ++q) {
            const int c = sub * 512 + q * 32 + lane;
            unsigned long long wd[4];
#pragma unroll
            for (int r = 0; r < 4; ++r)
                wd[r] = dup2(w1sh[(rq * 4 + r) * 1024 + c]);
#pragma unroll
            for (int bq = 0; bq < 4; ++bq) {
                const ulonglong2 yv = *reinterpret_cast<const ulonglong2*>(
                    &ysh4[bq * YS + c]);
#pragma unroll
                for (int r = 0; r < 4; ++r) {
                    fma2(acc[r][bq][0], wd[r], yv.x);
                    fma2(acc[r][bq][1], wd[r], yv.y);
                }
            }
        }

#pragma unroll
        for (int r = 0; r < 4; ++r)
#pragma unroll
            for (int bq = 0; bq < 4; ++bq)
#pragma unroll
                for (int e = 0; e < 2; ++e)
#pragma unroll
                    for (int off = 16; off; off >>= 1)
                        add2(acc[r][bq][e],
                             __shfl_xor_sync(0xffffffffu, acc[r][bq][e], off));

        if (lane < 16) {
            const int b  = lane;
            const int bq = b >> 2;
            const int e  = (b >> 1) & 1;
            const int hi = b & 1;
            float4 hv;
            {
                const float2 v0 = unpack2(acc[0][bq][e]);
                const float2 v1 = unpack2(acc[1][bq][e]);
                const float2 v2 = unpack2(acc[2][bq][e]);
                const float2 v3 = unpack2(acc[3][bq][e]);
                hv.x = hi ? v0.y : v0.x;
                hv.y = hi ? v1.y : v1.x;
                hv.z = hi ? v2.y : v2.x;
                hv.w = hi ? v3.y : v3.x;
            }
            const int slice = half * 2 + sub;
            const int m     = m0 + rq * 4;
            const int p     = m >> 7;
            const int k0    = m & 127;
            *reinterpret_cast<float4*>(
                &g_hp[slice * (P_ * B_ * CR_) + (p * B_ + b) * CR_ + k0]) = hv;
        }
    }

    grid_barrier(1, nblk);

    // ===== Phase C: att = sigmoid(W2 @ relu(h)) ==============================
    // unit = bid: p = bid>>3, 256-c tile = bid&7. 128 units.
    if (bid < 128) {
        float* w2sh = sm;                     // [256][W2S]
        float* hsh  = sm + 256 * W2S;         // [16][128]
        const int p  = bid >> 3;
        const int c0 = (bid & 7) * 256;

        // stage W2 tile via cp.async (256 rows x 128 k)
        const float* wsrc = W2 + (size_t)(p * C_ + c0) * CR_;
#pragma unroll
        for (int k = 0; k < 16; ++k) {
            const int i   = tid + k * NT;     // float4 index over 256x32
            const int row = i >> 5;
            const int qd  = i & 31;
            unsigned sa = (unsigned)__cvta_generic_to_shared(
                &w2sh[row * W2S + qd * 4]);
            asm volatile("cp.async.cg.shared.global [%0], [%1], 16;"
                         :: "r"(sa), "l"(wsrc + (size_t)row * CR_ + qd * 4));
        }
        asm volatile("cp.async.commit_group;");

        // combine 4 split-K partials + relu
        for (int i = tid; i < B_ * CR_; i += NT) {
            const float v = g_hp[p * (B_ * CR_) + i]
                          + g_hp[1 * (P_ * B_ * CR_) + p * (B_ * CR_) + i]
                          + g_hp[2 * (P_ * B_ * CR_) + p * (B_ * CR_) + i]
                          + g_hp[3 * (P_ * B_ * CR_) + p * (B_ * CR_) + i];
            hsh[i] = fmaxf(v, 0.f);
        }
        asm volatile("cp.async.wait_group 0;");
        __syncthreads();

        // thread = (c, b-group of 8)
        const int c  = c0 + (tid & 255);
        const int bg = tid >> 8;              // 0 or 1 (warp-uniform)
        const ulonglong2* wrow =
            reinterpret_cast<const ulonglong2*>(&w2sh[(tid & 255) * W2S]);
        const ulonglong2* h2 =
            reinterpret_cast<const ulonglong2*>(hsh + bg * 8 * CR_);

        unsigned long long acc[8];
#pragma unroll
        for (int j = 0; j < 8; ++j) acc[j] = 0ull;

#pragma unroll 4
        for (int kq = 0; kq < 32; ++kq) {
            const ulonglong2 w = wrow[kq];
#pragma unroll
            for (int j = 0; j < 8; ++j) {
                const ulonglong2 hv = h2[j * 32 + kq];   // uniform broadcast
                fma2(acc[j], w.x, hv.x);
                fma2(acc[j], w.y, hv.y);
            }
        }

#pragma unroll
        for (int j = 0; j < 8; ++j) {
            const int b = bg * 8 + j;
            const float2 v = unpack2(acc[j]);
            const float s = v.x + v.y;
            out[(size_t)(p * B_ + b) * C_ + c] = 1.f / (1.f + __expf(-s));
        }
    }
}

// -----------------------------------------------------------------------------
extern "C" void kernel_launch(void* const* d_in, const int* in_sizes, int n_in,
                              void* d_out, int out_size) {
    const float* x  = (const float*)d_in[0];
    const float* W1 = (const float*)d_in[1];
    const float* W2 = (const float*)d_in[2];
    float* out      = (float*)d_out;

    int dev = 0;
    cudaGetDevice(&dev);
    cudaDeviceProp prop;
    cudaGetDeviceProperties(&prop, dev);
    int nblk = prop.multiProcessorCount;
    if (nblk > 148) nblk = 148;
    if (nblk < 1) nblk = 1;

    cudaFuncSetAttribute(k_fused, cudaFuncAttributeMaxDynamicSharedMemorySize,
                         SMEM_BYTES);

    k_init<<<1, 32>>>();
    k_fused<<<nblk, NT, SMEM_BYTES>>>(x, W1, W2, out, nblk);
}

// round 8
// speedup vs baseline: 1.0404x; 1.0404x over previous
#include <cuda_runtime.h>
#include <cstddef>

// Problem constants
//   x  : (16, 2048, 64, 64) f32
//   W1 : (16, 128, 2048)    f32
//   W2 : (16, 2048, 128)    f32
//   out: (16, 16, 2048) f32
#define B_ 16
#define C_ 2048
#define P_ 16
#define CR_ 128
#define NPATCH 32768
#define NT 256

// Scratch (__device__ globals: allocation-free rule)
__device__ float    g_yT[C_ * B_];            // [c][b] patch means
__device__ float    g_hp[2 * P_ * B_ * CR_];  // split-K partial h
__device__ unsigned g_bar[4];                 // [0],[1]=barriers, [2]=work ctr

// f32x2 packed helpers -------------------------------------------------------
__device__ __forceinline__ void fma2(unsigned long long& d,
                                     unsigned long long a,
                                     unsigned long long b) {
    asm("fma.rn.f32x2 %0, %1, %2, %0;" : "+l"(d) : "l"(a), "l"(b));
}
__device__ __forceinline__ void add2(unsigned long long& d, unsigned long long v) {
    asm("add.rn.f32x2 %0, %0, %1;" : "+l"(d) : "l"(v));
}
__device__ __forceinline__ unsigned long long dup2(float w) {
    unsigned long long r;
    asm("mov.b64 %0, {%1, %1};" : "=l"(r) : "f"(w));
    return r;
}
__device__ __forceinline__ float2 unpack2(unsigned long long v) {
    float lo, hi;
    asm("mov.b64 {%0, %1}, %2;" : "=f"(lo), "=f"(hi) : "l"(v));
    return make_float2(lo, hi);
}

// grid barrier (all nblk blocks co-resident by construction) -----------------
__device__ __forceinline__ void grid_barrier(int ph, int nblk) {
    __syncthreads();
    if (threadIdx.x == 0) {
        __threadfence();
        atomicAdd(&g_bar[ph], 1u);
        while (*(volatile unsigned*)&g_bar[ph] < (unsigned)nblk) {
            __nanosleep(20);
        }
    }
    __syncthreads();
    __threadfence();
}

__global__ void k_init() {
    if (threadIdx.x < 4) g_bar[threadIdx.x] = 0u;
}

// -----------------------------------------------------------------------------
// Shared memory (floats):
//   phase B: w1sh[32][1024] (128 KB) | ysh4[4][YS] float4 (65.7 KB)
//   phase C: w2sh[256][W2S] (135 KB) | hsh[2048] (8 KB)
#define YS  1026
#define W2S 132
#define SMEM_BYTES (32 * 1024 * 4 + 4 * YS * 16)    // 196736 B

__global__ void __launch_bounds__(NT, 1)
k_fused(const float* __restrict__ x, const float* __restrict__ W1,
        const float* __restrict__ W2, float* __restrict__ out, int nblk) {
    extern __shared__ float sm[];
    const int tid  = threadIdx.x;
    const int warp = tid >> 5;
    const int lane = tid & 31;
    const int bid  = blockIdx.x;

    // ===== W1 tile prefetch via cp.async (overlaps phase A) =================
    if (bid < 128) {
        const int m0    = (bid >> 1) * 32;
        const int cbase = (bid & 1) * 1024;
        const float* gsrc0 = W1 + (size_t)m0 * C_ + cbase + tid * 4;
#pragma unroll
        for (int k = 0; k < 32; ++k) {
            unsigned sa = (unsigned)__cvta_generic_to_shared(
                &sm[k * 1024 + tid * 4]);
            asm volatile("cp.async.cg.shared.global [%0], [%1], 16;"
                         :: "r"(sa), "l"(gsrc0 + (size_t)k * C_));
        }
        asm volatile("cp.async.commit_group;");
    }

    // ===== W2 L2 prefetch (rides phase A's spare DRAM headroom) =============
    {
        const size_t W2_BYTES = (size_t)P_ * C_ * CR_ * 4;   // 16.8 MB
        const size_t base = (size_t)(bid * NT + tid) * 512;
        const char* wp = (const char*)W2 + base;
#pragma unroll
        for (int j = 0; j < 4; ++j) {
            if (base + j * 128 < W2_BYTES) {
                asm volatile("prefetch.global.L2 [%0];" :: "l"(wp + j * 128));
            }
        }
    }

    // ===== Phase A: 16x16 patch means, warp-level work stealing =============
    {
        const int g   = lane >> 3;       // patch within chunk
        const int sub = lane & 7;
        unsigned pg;
        if (lane == 0) pg = atomicAdd(&g_bar[2], 1u);
        pg = __shfl_sync(0xffffffffu, pg, 0);
        while (pg < NPATCH / 4) {
            const int patch = (int)pg * 4 + g;
            const float* base = x + (size_t)patch * 4096 + 16 * 64 + 16;
            float4 v[8];
#pragma unroll
            for (int t = 0; t < 8; ++t) {
                const int j = sub + t * 8;
                v[t] = __ldcs(reinterpret_cast<const float4*>(
                    base + (j >> 2) * 64 + (j & 3) * 4));
            }
            // steal next chunk while loads are in flight
            unsigned pg_next;
            if (lane == 0) pg_next = atomicAdd(&g_bar[2], 1u);

            float s = 0.f;
#pragma unroll
            for (int t = 0; t < 8; ++t)
                s += (v[t].x + v[t].y) + (v[t].z + v[t].w);
            s += __shfl_xor_sync(0xffffffffu, s, 4);
            s += __shfl_xor_sync(0xffffffffu, s, 2);
            s += __shfl_xor_sync(0xffffffffu, s, 1);
            if (sub == 0) {
                const int b = patch >> 11;
                const int c = patch & 2047;
                g_yT[c * B_ + b] = s * (1.f / 256.f);
            }
            pg = __shfl_sync(0xffffffffu, pg_next, 0);
        }
    }

    grid_barrier(0, nblk);

    // ===== Phase B: partial h = W1-half @ y ==================================
    if (bid < 128) {
        float*  w1sh = sm;
        float4* ysh4 = reinterpret_cast<float4*>(sm + 32 * 1024);
        const int m0    = (bid >> 1) * 32;
        const int half  = bid & 1;
        const int cbase = half * 1024;

        // stage y: ysh4[bq][c] (L2 hits)
#pragma unroll
        for (int k = 0; k < 16; ++k) {
            const int idx = tid + k * NT;
            const int c   = idx >> 2;
            const int bq  = idx & 3;
            ysh4[bq * YS + c] = *reinterpret_cast<const float4*>(
                &g_yT[(size_t)(cbase + c) * B_ + bq * 4]);
        }
        asm volatile("cp.async.wait_group 0;");
        __syncthreads();

        unsigned long long acc[4][4][2];
#pragma unroll
        for (int r = 0; r < 4; ++r)
#pragma unroll
            for (int bq = 0; bq < 4; ++bq) { acc[r][bq][0] = 0ull; acc[r][bq][1] = 0ull; }

#pragma unroll 4
        for (int q = 0; q < 32; ++q) {
            const int c = q * 32 + lane;
            unsigned long long wd[4];
#pragma unroll
            for (int r = 0; r < 4; ++r)
                wd[r] = dup2(w1sh[(warp * 4 + r) * 1024 + c]);
#pragma unroll
            for (int bq = 0; bq < 4; ++bq) {
                const ulonglong2 yv = *reinterpret_cast<const ulonglong2*>(
                    &ysh4[bq * YS + c]);
#pragma unroll
                for (int r = 0; r < 4; ++r) {
                    fma2(acc[r][bq][0], wd[r], yv.x);
                    fma2(acc[r][bq][1], wd[r], yv.y);
                }
            }
        }

#pragma unroll
        for (int r = 0; r < 4; ++r)
#pragma unroll
            for (int bq = 0; bq < 4; ++bq)
#pragma unroll
                for (int e = 0; e < 2; ++e)
#pragma unroll
                    for (int off = 16; off; off >>= 1)
                        add2(acc[r][bq][e],
                             __shfl_xor_sync(0xffffffffu, acc[r][bq][e], off));

        if (lane < 16) {
            const int b  = lane;
            const int bq = b >> 2;
            const int e  = (b >> 1) & 1;
            const int hi = b & 1;
            float4 hv;
            {
                const float2 v0 = unpack2(acc[0][bq][e]);
                const float2 v1 = unpack2(acc[1][bq][e]);
                const float2 v2 = unpack2(acc[2][bq][e]);
                const float2 v3 = unpack2(acc[3][bq][e]);
                hv.x = hi ? v0.y : v0.x;
                hv.y = hi ? v1.y : v1.x;
                hv.z = hi ? v2.y : v2.x;
                hv.w = hi ? v3.y : v3.x;
            }
            const int m  = m0 + warp * 4;
            const int p  = m >> 7;
            const int k0 = m & 127;
            *reinterpret_cast<float4*>(
                &g_hp[half * (P_ * B_ * CR_) + (p * B_ + b) * CR_ + k0]) = hv;
        }
    }

    grid_barrier(1, nblk);

    // ===== Phase C: att = sigmoid(W2 @ relu(h)) ==============================
    if (bid < 128) {
        float* w2sh = sm;                   // [256][W2S]
        float* hsh  = sm + 256 * W2S;       // [16][128]
        const int p  = bid >> 3;
        const int c0 = (bid & 7) * 256;

        // combine split-K partials + relu (L2 hits)
        for (int i = tid; i < B_ * CR_; i += NT) {
            const float v = g_hp[p * (B_ * CR_) + i]
                          + g_hp[P_ * B_ * CR_ + p * (B_ * CR_) + i];
            hsh[i] = fmaxf(v, 0.f);
        }
        // stage W2 tile (256 rows x 128 k) — L2-resident from prefetch
        const float4* wsrc = reinterpret_cast<const float4*>(
            W2 + (size_t)(p * C_ + c0) * CR_);
#pragma unroll
        for (int k = 0; k < 32; ++k) {
            const int i   = tid + k * NT;
            const int row = i >> 5;
            const int qd  = i & 31;
            *reinterpret_cast<float4*>(&w2sh[row * W2S + qd * 4]) = wsrc[i];
        }
        __syncthreads();

        const ulonglong2* wrow = reinterpret_cast<const ulonglong2*>(&w2sh[tid * W2S]);
        const ulonglong2* h2   = reinterpret_cast<const ulonglong2*>(hsh);

        unsigned long long acc[16];
#pragma unroll
        for (int b = 0; b < B_; ++b) acc[b] = 0ull;

#pragma unroll 4
        for (int kq = 0; kq < 32; ++kq) {
            const ulonglong2 w = wrow[kq];
#pragma unroll
            for (int b = 0; b < B_; ++b) {
                const ulonglong2 hv = h2[b * 32 + kq];   // uniform broadcast
                fma2(acc[b], w.x, hv.x);
                fma2(acc[b], w.y, hv.y);
            }
        }

        const int c = c0 + tid;
#pragma unroll
        for (int b = 0; b < B_; ++b) {
            const float2 v = unpack2(acc[b]);
            const float s = v.x + v.y;
            out[(size_t)(p * B_ + b) * C_ + c] = 1.f / (1.f + __expf(-s));
        }
    }
}

// -----------------------------------------------------------------------------
extern "C" void kernel_launch(void* const* d_in, const int* in_sizes, int n_in,
                              void* d_out, int out_size) {
    const float* x  = (const float*)d_in[0];
    const float* W1 = (const float*)d_in[1];
    const float* W2 = (const float*)d_in[2];
    float* out      = (float*)d_out;

    int dev = 0;
    cudaGetDevice(&dev);
    cudaDeviceProp prop;
    cudaGetDeviceProperties(&prop, dev);
    int nblk = prop.multiProcessorCount;
    if (nblk > 148) nblk = 148;
    if (nblk < 1) nblk = 1;

    cudaFuncSetAttribute(k_fused, cudaFuncAttributeMaxDynamicSharedMemorySize,
                         SMEM_BYTES);

    k_init<<<1, 32>>>();
    k_fused<<<nblk, NT, SMEM_BYTES>>>(x, W1, W2, out, nblk);
}

// round 9
// speedup vs baseline: 1.1172x; 1.0738x over previous
#include <cuda_runtime.h>
#include <cstddef>

// Problem constants
//   x  : (16, 2048, 64, 64) f32
//   W1 : (16, 128, 2048)    f32
//   W2 : (16, 2048, 128)    f32
//   out: (16, 16, 2048) f32
#define B_ 16
#define C_ 2048
#define P_ 16
#define CR_ 128
#define NPATCH 32768
#define NBLK2 128

// Scratch (__device__ globals: allocation-free rule)
__device__ float    g_yT[C_ * B_];            // [c][b] patch means
__device__ float    g_hp[2 * P_ * B_ * CR_];  // split-K partial h
__device__ unsigned g_bar[4];                 // grid-barrier counters

// f32x2 packed helpers -------------------------------------------------------
__device__ __forceinline__ void fma2(unsigned long long& d,
                                     unsigned long long a,
                                     unsigned long long b) {
    asm("fma.rn.f32x2 %0, %1, %2, %0;" : "+l"(d) : "l"(a), "l"(b));
}
__device__ __forceinline__ void add2(unsigned long long& d, unsigned long long v) {
    asm("add.rn.f32x2 %0, %0, %1;" : "+l"(d) : "l"(v));
}
__device__ __forceinline__ unsigned long long dup2(float w) {
    unsigned long long r;
    asm("mov.b64 %0, {%1, %1};" : "=l"(r) : "f"(w));
    return r;
}
__device__ __forceinline__ float2 unpack2(unsigned long long v) {
    float lo, hi;
    asm("mov.b64 {%0, %1}, %2;" : "=f"(lo), "=f"(hi) : "l"(v));
    return make_float2(lo, hi);
}

// grid barrier (128 blocks, all co-resident: 1 block/SM by smem) -------------
__device__ __forceinline__ void grid_barrier(int ph, int nblk) {
    __syncthreads();
    if (threadIdx.x == 0) {
        __threadfence();
        atomicAdd(&g_bar[ph], 1u);
        while (*(volatile unsigned*)&g_bar[ph] < (unsigned)nblk) {
            __nanosleep(20);
        }
    }
    __syncthreads();
    __threadfence();
}

// ---------------------------------------------------------------------------
// Kernel A: 16x16 patch mean. 8 lanes/patch, 4 patches/warp, grid 1024.
// Proven 14.0 us @ 4.85 TB/s. Also resets barrier counters for kernel B.
// ---------------------------------------------------------------------------
__global__ void __launch_bounds__(256) k_mean(const float* __restrict__ x,
                                              float* __restrict__ yT) {
    if (blockIdx.x == 0 && threadIdx.x < 4) g_bar[threadIdx.x] = 0u;

    const int warp  = blockIdx.x * 8 + (threadIdx.x >> 5);   // 0..8191
    const int lane  = threadIdx.x & 31;
    const int g     = lane >> 3;       // patch within warp
    const int sub   = lane & 7;
    const int patch = warp * 4 + g;    // 0..32767
    const float* base = x + (size_t)patch * 4096 + 16 * 64 + 16;

    float s = 0.f;
#pragma unroll
    for (int t = 0; t < 8; ++t) {
        const int j = sub + t * 8;     // float4 index 0..63 in patch
        const float4 v = __ldcs(reinterpret_cast<const float4*>(
            base + (j >> 2) * 64 + (j & 3) * 4));
        s += (v.x + v.y) + (v.z + v.w);
    }
    s += __shfl_xor_sync(0xffffffffu, s, 4);
    s += __shfl_xor_sync(0xffffffffu, s, 2);
    s += __shfl_xor_sync(0xffffffffu, s, 1);

    if (sub == 0) {
        const int b = patch >> 11;
        const int c = patch & 2047;
        yT[c * B_ + b] = s * (1.f / 256.f);
    }
}

// ---------------------------------------------------------------------------
// Kernel B: persistent gemm1 + gemm2, 128 blocks, 1 grid barrier.
// Shared memory (floats):
//   phase B: w1sh[32][1024] (128 KB) | ysh4[4][YS] float4 (65.7 KB)
//   phase C: w2sh[256][W2S] (135 KB) | hsh[2048] (8 KB)
// ---------------------------------------------------------------------------
#define YS  1026
#define W2S 132
#define SMEM_BYTES (32 * 1024 * 4 + 4 * YS * 16)    // 196736 B

__global__ void __launch_bounds__(256, 1)
k_gemm12(const float* __restrict__ W1, const float* __restrict__ W2,
         const float* __restrict__ yT, float* __restrict__ out) {
    extern __shared__ float sm[];
    const int tid  = threadIdx.x;
    const int warp = tid >> 5;
    const int lane = tid & 31;
    const int bid  = blockIdx.x;

    // ===== stage W1 tile via cp.async (whole chip streams 16.8 MB) ==========
    const int m0    = (bid >> 1) * 32;
    const int half  = bid & 1;
    const int cbase = half * 1024;
    {
        const float* gsrc0 = W1 + (size_t)m0 * C_ + cbase + tid * 4;
#pragma unroll
        for (int k = 0; k < 32; ++k) {
            unsigned sa = (unsigned)__cvta_generic_to_shared(
                &sm[k * 1024 + tid * 4]);
            asm volatile("cp.async.cg.shared.global [%0], [%1], 16;"
                         :: "r"(sa), "l"(gsrc0 + (size_t)k * C_));
        }
        asm volatile("cp.async.commit_group;");
    }

    // ===== W2 -> L2 prefetch (fills DRAM-idle window during B compute) ======
    {
        const char* wp = (const char*)W2 + (size_t)(bid * 256 + tid) * 512;
#pragma unroll
        for (int j = 0; j < 4; ++j)
            asm volatile("prefetch.global.L2 [%0];" :: "l"(wp + j * 128));
    }

    // ===== stage y half: ysh4[bq][c] (L2 hits; yT just written) =============
    {
        float4* ysh4 = reinterpret_cast<float4*>(sm + 32 * 1024);
#pragma unroll
        for (int k = 0; k < 16; ++k) {
            const int idx = tid + k * 256;
            const int c   = idx >> 2;
            const int bq  = idx & 3;
            ysh4[bq * YS + c] = *reinterpret_cast<const float4*>(
                &yT[(size_t)(cbase + c) * B_ + bq * 4]);
        }
    }
    asm volatile("cp.async.wait_group 0;");
    __syncthreads();

    // ===== Phase B: partial h = W1-half @ y ==================================
    {
        float*  w1sh = sm;
        float4* ysh4 = reinterpret_cast<float4*>(sm + 32 * 1024);

        unsigned long long acc[4][4][2];
#pragma unroll
        for (int r = 0; r < 4; ++r)
#pragma unroll
            for (int bq = 0; bq < 4; ++bq) { acc[r][bq][0] = 0ull; acc[r][bq][1] = 0ull; }

#pragma unroll 4
        for (int q = 0; q < 32; ++q) {
            const int c = q * 32 + lane;
            unsigned long long wd[4];
#pragma unroll
            for (int r = 0; r < 4; ++r)
                wd[r] = dup2(w1sh[(warp * 4 + r) * 1024 + c]);
#pragma unroll
            for (int bq = 0; bq < 4; ++bq) {
                const ulonglong2 yv = *reinterpret_cast<const ulonglong2*>(
                    &ysh4[bq * YS + c]);
#pragma unroll
                for (int r = 0; r < 4; ++r) {
                    fma2(acc[r][bq][0], wd[r], yv.x);
                    fma2(acc[r][bq][1], wd[r], yv.y);
                }
            }
        }

#pragma unroll
        for (int r = 0; r < 4; ++r)
#pragma unroll
            for (int bq = 0; bq < 4; ++bq)
#pragma unroll
                for (int e = 0; e < 2; ++e)
#pragma unroll
                    for (int off = 16; off; off >>= 1)
                        add2(acc[r][bq][e],
                             __shfl_xor_sync(0xffffffffu, acc[r][bq][e], off));

        if (lane < 16) {
            const int b  = lane;
            const int bq = b >> 2;
            const int e  = (b >> 1) & 1;
            const int hi = b & 1;
            float4 hv;
            {
                const float2 v0 = unpack2(acc[0][bq][e]);
                const float2 v1 = unpack2(acc[1][bq][e]);
                const float2 v2 = unpack2(acc[2][bq][e]);
                const float2 v3 = unpack2(acc[3][bq][e]);
                hv.x = hi ? v0.y : v0.x;
                hv.y = hi ? v1.y : v1.x;
                hv.z = hi ? v2.y : v2.x;
                hv.w = hi ? v3.y : v3.x;
            }
            const int m  = m0 + warp * 4;
            const int p  = m >> 7;
            const int k0 = m & 127;
            *reinterpret_cast<float4*>(
                &g_hp[half * (P_ * B_ * CR_) + (p * B_ + b) * CR_ + k0]) = hv;
        }
    }

    grid_barrier(0, NBLK2);

    // ===== Phase C: att = sigmoid(W2 @ relu(h)) ==============================
    {
        float* w2sh = sm;                   // [256][W2S]
        float* hsh  = sm + 256 * W2S;       // [16][128]
        const int p  = bid >> 3;
        const int c0 = (bid & 7) * 256;

        // stage W2 tile via cp.async (hits L2 thanks to prefetch)
        const float* wsrc = W2 + (size_t)(p * C_ + c0) * CR_;
#pragma unroll
        for (int k = 0; k < 32; ++k) {
            const int i   = tid + k * 256;   // float4 index over 256x32
            const int row = i >> 5;
            const int qd  = i & 31;
            unsigned sa = (unsigned)__cvta_generic_to_shared(
                &w2sh[row * W2S + qd * 4]);
            asm volatile("cp.async.cg.shared.global [%0], [%1], 16;"
                         :: "r"(sa), "l"(wsrc + (size_t)row * CR_ + qd * 4));
        }
        asm volatile("cp.async.commit_group;");

        // combine split-K partials + relu (L2 hits)
        for (int i = tid; i < B_ * CR_; i += 256) {
            const float v = g_hp[p * (B_ * CR_) + i]
                          + g_hp[P_ * B_ * CR_ + p * (B_ * CR_) + i];
            hsh[i] = fmaxf(v, 0.f);
        }
        asm volatile("cp.async.wait_group 0;");
        __syncthreads();

        const ulonglong2* wrow = reinterpret_cast<const ulonglong2*>(&w2sh[tid * W2S]);
        const ulonglong2* h2   = reinterpret_cast<const ulonglong2*>(hsh);

        unsigned long long acc[16];
#pragma unroll
        for (int b = 0; b < B_; ++b) acc[b] = 0ull;

#pragma unroll 4
        for (int kq = 0; kq < 32; ++kq) {
            const ulonglong2 w = wrow[kq];
#pragma unroll
            for (int b = 0; b < B_; ++b) {
                const ulonglong2 hv = h2[b * 32 + kq];   // uniform broadcast
                fma2(acc[b], w.x, hv.x);
                fma2(acc[b], w.y, hv.y);
            }
        }

        const int c = c0 + tid;
#pragma unroll
        for (int b = 0; b < B_; ++b) {
            const float2 v = unpack2(acc[b]);
            const float s = v.x + v.y;
            out[(size_t)(p * B_ + b) * C_ + c] = 1.f / (1.f + __expf(-s));
        }
    }
}

// -----------------------------------------------------------------------------
extern "C" void kernel_launch(void* const* d_in, const int* in_sizes, int n_in,
                              void* d_out, int out_size) {
    const float* x  = (const float*)d_in[0];
    const float* W1 = (const float*)d_in[1];
    const float* W2 = (const float*)d_in[2];
    float* out      = (float*)d_out;

    float* yT;
    cudaGetSymbolAddress((void**)&yT, g_yT);

    cudaFuncSetAttribute(k_gemm12, cudaFuncAttributeMaxDynamicSharedMemorySize,
                         SMEM_BYTES);

    k_mean  <<<1024, 256>>>(x, yT);
    k_gemm12<<<NBLK2, 256, SMEM_BYTES>>>(W1, W2, yT, out);
}